// round 15
// baseline (speedup 1.0000x reference)
#include <cuda_runtime.h>
#include <cuda_bf16.h>
#include <cstdint>

// Problem: B=4, L=2048, H=8, D=64.
// Reference math collapses: out[b,q,h,d] = (sum_w softmax[.]) * (sum_e V[b,e,h,d])
//                                        = 1 * sum_l V[b,l,h,d]
// Q, K dead inputs. Column-sum V over L, broadcast over q.
//
// R15: overlap the read stream with the write stream via a forked graph.
// R14 proved launch overhead is small and phases don't overlap when
// serialized; traffic is fixed (16.8MB each way) so the only lever left is
// concurrency between directions. DAG: R_A(b0,b1) -> R_B(b2,b3) on main
// stream; W_A forks after R_A and overlaps R_B; W_B follows. Reduction is
// the proven deterministic int64 fixed-point REDG (kills stage-2); W kernels
// self-zero the accumulator via a last-block counter (replay-safe).

#define B_DIM 4
#define L_DIM 2048
#define HD 512                  // floats per (b,l) row
#define HD4 128                 // float4 per row
#define R_ROWS 8                // rows per read block (16 KB tile)
#define R_TILE_BYTES (R_ROWS * HD * 4)     // 16384
#define W_ROWS 16               // q rows per write block (32 KB tile)
#define W_TILE_BYTES (W_ROWS * HD * 4)     // 32768

#define ACC_SCALE  68719476736.0        // 2^36
#define ACC_INV    (1.0 / 68719476736.0)

// Scratch (allocation-free __device__ globals; zero-initialized at load)
__device__ long long g_acc[B_DIM * HD];   // 16 KB, L2-resident
__device__ unsigned g_wc[2] = {0u, 0u};   // per write-kernel arrival counters

__device__ __forceinline__ float4 f4add(float4 a, float4 b) {
    a.x += b.x; a.y += b.y; a.z += b.z; a.w += b.w; return a;
}
__device__ __forceinline__ uint32_t smem_u32(const void* p) {
    return (uint32_t)__cvta_generic_to_shared(p);
}
__device__ __forceinline__ void red_add_ll(long long* p, long long v) {
    asm volatile("red.global.add.u64 [%0], %1;" :: "l"(p), "l"(v) : "memory");
}

// Read kernel: 512 blocks x 128 thr covering 2 batches (bbase, bbase+1).
// Each block: one 16 KB TMA chunk (8 rows), fold to 512 floats, 4 REDGs
// per thread into the fixed-point accumulator. Kernel boundary = sync.
__global__ void __launch_bounds__(128) read_kernel(const float* __restrict__ V,
                                                   int bbase) {
    __shared__ alignas(128) float4 tile[R_ROWS * HD4];   // 16 KB
    __shared__ alignas(8) unsigned long long mbar;

    const int t = threadIdx.x;
    const int b = bbase + (blockIdx.x >> 8);   // 256 chunks per batch
    const int chunk = blockIdx.x & 255;
    const uint32_t mb = smem_u32(&mbar);

    if (t == 0)
        asm volatile("mbarrier.init.shared.b64 [%0], 1;" :: "r"(mb) : "memory");
    __syncthreads();
    if (t == 0) {
        asm volatile("mbarrier.arrive.expect_tx.shared.b64 _, [%0], %1;"
                     :: "r"(mb), "r"((uint32_t)R_TILE_BYTES) : "memory");
        const float* src = V + ((size_t)(b * L_DIM + chunk * R_ROWS)) * HD;
        asm volatile(
            "cp.async.bulk.shared::cluster.global.mbarrier::complete_tx::bytes "
            "[%0], [%1], %2, [%3];"
            :: "r"(smem_u32(tile)), "l"(src), "r"((uint32_t)R_TILE_BYTES), "r"(mb)
            : "memory");
    }
    uint32_t done = 0;
    do {
        asm volatile(
            "{\n\t.reg .pred q;\n\t"
            "mbarrier.try_wait.parity.shared.b64 q, [%1], 0;\n\t"
            "selp.b32 %0, 1, 0, q;\n\t}"
            : "=r"(done) : "r"(mb) : "memory");
    } while (!done);

    // Fold 8 rows at float4-column t (LDS.128, conflict-free).
    float4 a0 = f4add(tile[0 * HD4 + t], tile[1 * HD4 + t]);
    float4 a1 = f4add(tile[2 * HD4 + t], tile[3 * HD4 + t]);
    float4 a2 = f4add(tile[4 * HD4 + t], tile[5 * HD4 + t]);
    float4 a3 = f4add(tile[6 * HD4 + t], tile[7 * HD4 + t]);
    float4 s = f4add(f4add(a0, a1), f4add(a2, a3));

    long long* acc = &g_acc[b * HD + t * 4];
    red_add_ll(&acc[0], __double2ll_rn((double)s.x * ACC_SCALE));
    red_add_ll(&acc[1], __double2ll_rn((double)s.y * ACC_SCALE));
    red_add_ll(&acc[2], __double2ll_rn((double)s.z * ACC_SCALE));
    red_add_ll(&acc[3], __double2ll_rn((double)s.w * ACC_SCALE));
}

// Write kernel: 256 blocks x 128 thr covering 2 batches. Each block reads
// its batch's 4 KB acc slice (L2-hot), builds a 32 KB broadcast tile
// (16 q rows), bulk-stores it, then the LAST block to finish zeroes the
// acc slices + counter so the next replay starts clean (deterministic).
__global__ void __launch_bounds__(128) write_kernel(float* __restrict__ out,
                                                    int bbase, int wc_idx) {
    __shared__ alignas(128) float4 tile[W_ROWS * HD4];   // 32 KB
    __shared__ int s_last;

    const int t = threadIdx.x;
    const int b = bbase + (blockIdx.x >> 7);   // 128 chunks per batch
    const int chunk = blockIdx.x & 127;

    const long long* acc = &g_acc[b * HD + t * 4];
    float4 v;
    v.x = (float)((double)acc[0] * ACC_INV);
    v.y = (float)((double)acc[1] * ACC_INV);
    v.z = (float)((double)acc[2] * ACC_INV);
    v.w = (float)((double)acc[3] * ACC_INV);

#pragma unroll
    for (int i = 0; i < W_ROWS; ++i)
        tile[i * HD4 + t] = v;                 // STS.128, conflict-free
    __syncthreads();

    if (t == 0) {
        asm volatile("fence.proxy.async;" ::: "memory");
        float* dst = out + ((size_t)(b * L_DIM + chunk * W_ROWS)) * HD;
        asm volatile(
            "cp.async.bulk.global.shared::cta.bulk_group [%0], [%1], %2;"
            :: "l"(dst), "r"(smem_u32(tile)), "r"((uint32_t)W_TILE_BYTES)
            : "memory");
        asm volatile("cp.async.bulk.commit_group;" ::: "memory");
        asm volatile("cp.async.bulk.wait_group 0;" ::: "memory");
    }

    // Replay-safe cleanup: last of the 256 blocks zeroes this kernel's two
    // acc slices and resets the counter. All blocks' acc reads completed
    // before their arrival (loads feed the tile before __syncthreads).
    if (t == 0) {
        __threadfence();
        unsigned a = atomicAdd(&g_wc[wc_idx], 1u);
        s_last = (a == 255u) ? 1 : 0;
    }
    __syncthreads();
    if (s_last) {
        long long* z = &g_acc[bbase * HD];     // 1024 entries (2 batches)
        for (int i = t; i < 2 * HD; i += 128)
            z[i] = 0ll;
        if (t == 0) {
            __threadfence();
            g_wc[wc_idx] = 0u;
        }
    }
}

extern "C" void kernel_launch(void* const* d_in, const int* in_sizes, int n_in,
                              void* d_out, int out_size) {
    // inputs: [0] queries, [1] keys, [2] values (float32). Q, K unused by math.
    const float* V = (const float*)d_in[2];
    float* out = (float*)d_out;

    // Forked DAG: main stream runs R_A -> R_B -> W_B; W_A forks off after
    // R_A and overlaps R_B; join before returning. Stream/event objects are
    // created unconditionally each call (identical work every call).
    cudaStream_t s1;
    cudaStreamCreateWithFlags(&s1, cudaStreamNonBlocking);
    cudaEvent_t eA, eW;
    cudaEventCreateWithFlags(&eA, cudaEventDisableTiming);
    cudaEventCreateWithFlags(&eW, cudaEventDisableTiming);

    read_kernel<<<512, 128>>>(V, 0);            // batches 0,1 -> g_acc
    cudaEventRecord(eA, 0);
    cudaStreamWaitEvent(s1, eA, 0);
    write_kernel<<<256, 128, 0, s1>>>(out, 0, 0);   // overlaps next read
    cudaEventRecord(eW, s1);

    read_kernel<<<512, 128>>>(V, 2);            // batches 2,3
    write_kernel<<<256, 128>>>(out, 2, 1);
    cudaStreamWaitEvent(0, eW, 0);              // join fork
}

// round 16
// speedup vs baseline: 1.2156x; 1.2156x over previous
#include <cuda_runtime.h>
#include <cuda_bf16.h>
#include <cstdint>

// Problem: B=4, L=2048, H=8, D=64.
// Reference math collapses: out[b,q,h,d] = (sum_w softmax[.]) * (sum_e V[b,e,h,d])
//                                        = 1 * sum_l V[b,l,h,d]
// Q, K dead inputs. Column-sum V over L, broadcast over q.
//
// R16: two plain kernels on one stream (the structures that beat everything
// else), combining the two proven wins:
//  - read_kernel: R7's best reader (1024 x 128, 16KB TMA tile, smem fold)
//    + deterministic int64 fixed-point REDG => stage-2 kernel deleted.
//  - write_kernel: posted STG.128 broadcast (R15 showed TMA bulk stores at
//    low occupancy serialize on wait_group; plain stores post and retire).
//    Last block re-zeroes g_acc for graph-replay determinism.

#define B_DIM 4
#define L_DIM 2048
#define HD 512                  // floats per (b,l) row
#define HD4 128                 // float4 per row
#define R_ROWS 8                // rows per read block (16 KB tile)
#define R_TILE_BYTES (R_ROWS * HD * 4)     // 16384
#define W_ROWS 8                // q rows per write block
#define W_BLOCKS (B_DIM * (L_DIM / W_ROWS))   // 1024

#define ACC_SCALE  68719476736.0        // 2^36
#define ACC_INV    (1.0 / 68719476736.0)

// Scratch (allocation-free __device__ globals; zero-initialized at load)
__device__ long long g_acc[B_DIM * HD];   // 16 KB, L2-resident
__device__ unsigned g_wc = 0;             // write-kernel arrival counter

__device__ __forceinline__ float4 f4add(float4 a, float4 b) {
    a.x += b.x; a.y += b.y; a.z += b.z; a.w += b.w; return a;
}
__device__ __forceinline__ uint32_t smem_u32(const void* p) {
    return (uint32_t)__cvta_generic_to_shared(p);
}
__device__ __forceinline__ void red_add_ll(long long* p, long long v) {
    asm volatile("red.global.add.u64 [%0], %1;" :: "l"(p), "l"(v) : "memory");
}
__device__ __forceinline__ long long ld_cg_ll(const long long* p) {
    long long v;
    asm volatile("ld.global.cg.u64 %0, [%1];" : "=l"(v) : "l"(p));
    return v;
}

// Read: 1024 blocks x 128 threads. One 16 KB TMA chunk (8 V rows), fold to
// 512 column floats, 4 REDGs/thread into the fixed-point accumulator.
// Kernel boundary is the only sync needed.
__global__ void __launch_bounds__(128) read_kernel(const float* __restrict__ V) {
    __shared__ alignas(128) float4 tile[R_ROWS * HD4];   // 16 KB
    __shared__ alignas(8) unsigned long long mbar;

    const int t = threadIdx.x;
    const int b = blockIdx.x >> 8;             // 256 chunks per batch
    const int chunk = blockIdx.x & 255;
    const uint32_t mb = smem_u32(&mbar);

    if (t == 0)
        asm volatile("mbarrier.init.shared.b64 [%0], 1;" :: "r"(mb) : "memory");
    __syncthreads();
    if (t == 0) {
        asm volatile("mbarrier.arrive.expect_tx.shared.b64 _, [%0], %1;"
                     :: "r"(mb), "r"((uint32_t)R_TILE_BYTES) : "memory");
        const float* src = V + ((size_t)(b * L_DIM + chunk * R_ROWS)) * HD;
        asm volatile(
            "cp.async.bulk.shared::cluster.global.mbarrier::complete_tx::bytes "
            "[%0], [%1], %2, [%3];"
            :: "r"(smem_u32(tile)), "l"(src), "r"((uint32_t)R_TILE_BYTES), "r"(mb)
            : "memory");
    }
    uint32_t done = 0;
    do {
        asm volatile(
            "{\n\t.reg .pred q;\n\t"
            "mbarrier.try_wait.parity.shared.b64 q, [%1], 0;\n\t"
            "selp.b32 %0, 1, 0, q;\n\t}"
            : "=r"(done) : "r"(mb) : "memory");
    } while (!done);

    // Fold 8 rows at float4-column t (LDS.128, conflict-free).
    float4 a0 = f4add(tile[0 * HD4 + t], tile[1 * HD4 + t]);
    float4 a1 = f4add(tile[2 * HD4 + t], tile[3 * HD4 + t]);
    float4 a2 = f4add(tile[4 * HD4 + t], tile[5 * HD4 + t]);
    float4 a3 = f4add(tile[6 * HD4 + t], tile[7 * HD4 + t]);
    float4 s = f4add(f4add(a0, a1), f4add(a2, a3));

    long long* acc = &g_acc[b * HD + t * 4];
    red_add_ll(&acc[0], __double2ll_rn((double)s.x * ACC_SCALE));
    red_add_ll(&acc[1], __double2ll_rn((double)s.y * ACC_SCALE));
    red_add_ll(&acc[2], __double2ll_rn((double)s.z * ACC_SCALE));
    red_add_ll(&acc[3], __double2ll_rn((double)s.w * ACC_SCALE));
}

// Write: 1024 blocks x 128 threads. Thread t converts its 32-byte acc slice
// (L2-hot, 16 KB total) and posts 8 STG.128 over 8 q rows. No completion
// waits. Last block to arrive re-zeroes g_acc + counter (replay-safe: every
// block's acc reads precede its fence+arrival).
__global__ void __launch_bounds__(128) write_kernel(float* __restrict__ out) {
    __shared__ int s_last;
    const int t = threadIdx.x;
    const int b = blockIdx.x >> 8;             // 256 chunks per batch
    const int chunk = blockIdx.x & 255;

    const long long* acc = &g_acc[b * HD + t * 4];
    float4 v;
    v.x = (float)((double)ld_cg_ll(&acc[0]) * ACC_INV);
    v.y = (float)((double)ld_cg_ll(&acc[1]) * ACC_INV);
    v.z = (float)((double)ld_cg_ll(&acc[2]) * ACC_INV);
    v.w = (float)((double)ld_cg_ll(&acc[3]) * ACC_INV);

    float4* dst = reinterpret_cast<float4*>(
        out + ((size_t)(b * L_DIM + chunk * W_ROWS)) * HD) + t;
#pragma unroll
    for (int i = 0; i < W_ROWS; ++i)
        dst[(size_t)i * HD4] = v;              // posted STG.128

    // Replay-safe accumulator cleanup.
    if (t == 0) {
        __threadfence();
        unsigned a = atomicAdd(&g_wc, 1u);
        s_last = (a == (unsigned)(W_BLOCKS - 1)) ? 1 : 0;
    }
    __syncthreads();
    if (s_last) {
        for (int i = t; i < B_DIM * HD; i += 128)
            g_acc[i] = 0ll;
        if (t == 0) {
            __threadfence();
            g_wc = 0u;
        }
    }
}

extern "C" void kernel_launch(void* const* d_in, const int* in_sizes, int n_in,
                              void* d_out, int out_size) {
    // inputs: [0] queries, [1] keys, [2] values (float32). Q, K unused by math.
    const float* V = (const float*)d_in[2];
    float* out = (float*)d_out;

    read_kernel<<<B_DIM * (L_DIM / R_ROWS) / 1, 128>>>(V);   // 1024 blocks
    write_kernel<<<W_BLOCKS, 128>>>(out);
}